// round 1
// baseline (speedup 1.0000x reference)
#include <cuda_runtime.h>
#include <math.h>

#define H 16
#define HS 128
#define ROT 32
#define S_LEN 2048
#define B_SZ 2
#define D_MODEL 2048
#define N_QKV (3 * H * HS)          // 6144
#define M_ROWS (B_SZ * S_LEN)       // 4096
#define SCALE 0.08838834764831845f  // 1/sqrt(128)

// Scratch (allocation-guard-safe __device__ globals)
__device__ float g_qkv[(size_t)M_ROWS * N_QKV];     // (4096, 6144) = qkv projection
__device__ float g_attn[(size_t)M_ROWS * H * HS];   // (4096, 2048) = attention output

// ---------------------------------------------------------------------------
// Tiled SGEMM + bias: C[M,N] = A[M,K] @ B[K,N] + bias[N]
// BM=BN=128, BK=8, 256 threads, 8x8 per-thread microtile.
// ---------------------------------------------------------------------------
__global__ __launch_bounds__(256) void sgemm_bias(
    const float* __restrict__ A, const float* __restrict__ Bm,
    const float* __restrict__ bias, float* __restrict__ C,
    int M, int N, int K)
{
    __shared__ float As[8][128];
    __shared__ float Bs[8][128];

    const int tid = threadIdx.x;
    const int row0 = blockIdx.y * 128;
    const int col0 = blockIdx.x * 128;
    const int trow = (tid >> 4) << 3;   // (tid/16)*8
    const int tcol = (tid & 15) << 3;   // (tid%16)*8

    const int ar  = tid >> 1;           // 0..127
    const int ak4 = (tid & 1) * 4;      // 0 or 4
    const int bk  = tid >> 5;           // 0..7
    const int bn4 = (tid & 31) * 4;     // 0..124

    const float* Aptr = A + (size_t)(row0 + ar) * K + ak4;
    const float* Bptr = Bm + (size_t)bk * N + col0 + bn4;

    float acc[8][8];
#pragma unroll
    for (int i = 0; i < 8; i++)
#pragma unroll
        for (int j = 0; j < 8; j++) acc[i][j] = 0.0f;

    for (int k0 = 0; k0 < K; k0 += 8) {
        float4 va = *(const float4*)(Aptr + k0);
        float4 vb = *(const float4*)(Bptr + (size_t)k0 * N);
        __syncthreads();
        As[ak4 + 0][ar] = va.x;
        As[ak4 + 1][ar] = va.y;
        As[ak4 + 2][ar] = va.z;
        As[ak4 + 3][ar] = va.w;
        *(float4*)&Bs[bk][bn4] = vb;
        __syncthreads();
#pragma unroll
        for (int kk = 0; kk < 8; kk++) {
            float a[8], b[8];
            *(float4*)(a)     = *(const float4*)&As[kk][trow];
            *(float4*)(a + 4) = *(const float4*)&As[kk][trow + 4];
            *(float4*)(b)     = *(const float4*)&Bs[kk][tcol];
            *(float4*)(b + 4) = *(const float4*)&Bs[kk][tcol + 4];
#pragma unroll
            for (int i = 0; i < 8; i++)
#pragma unroll
                for (int j = 0; j < 8; j++)
                    acc[i][j] += a[i] * b[j];
        }
    }

    float bb[8];
#pragma unroll
    for (int j = 0; j < 8; j++) bb[j] = bias[col0 + tcol + j];

#pragma unroll
    for (int i = 0; i < 8; i++) {
        size_t row = (size_t)(row0 + trow + i);
        float4 o0 = make_float4(acc[i][0] + bb[0], acc[i][1] + bb[1],
                                acc[i][2] + bb[2], acc[i][3] + bb[3]);
        float4 o1 = make_float4(acc[i][4] + bb[4], acc[i][5] + bb[5],
                                acc[i][6] + bb[6], acc[i][7] + bb[7]);
        *(float4*)&C[row * N + col0 + tcol]     = o0;
        *(float4*)&C[row * N + col0 + tcol + 4] = o1;
    }
}

// ---------------------------------------------------------------------------
// RoPE (NeoX, partial ROT=32) applied in place to q and k in g_qkv.
// One thread per (b, s, h, j), j in [0,16): rotates pairs (j, j+16) for q and k.
// ---------------------------------------------------------------------------
__global__ void rope_kernel(const int* __restrict__ pos_ids)
{
    int idx = blockIdx.x * blockDim.x + threadIdx.x;
    const int total = B_SZ * S_LEN * H * (ROT / 2);
    if (idx >= total) return;

    int j = idx & 15;            // 0..15
    int t = idx >> 4;
    int h = t % H;  t /= H;
    int s = t % S_LEN;
    int b = t / S_LEN;

    int p = pos_ids[b * S_LEN + s];
    double f = pow(10000.0, -(double)(2 * j) / (double)ROT);
    double ang = (double)p * f;
    float c  = (float)cos(ang);
    float sn = (float)sin(ang);

    size_t base = ((size_t)(b * S_LEN + s) * H + h) * (size_t)(3 * HS);
    float* q = g_qkv + base;
    float q1 = q[j], q2 = q[j + 16];
    q[j]      = q1 * c - q2 * sn;
    q[j + 16] = q2 * c + q1 * sn;

    float* k = g_qkv + base + HS;
    float k1 = k[j], k2 = k[j + 16];
    k[j]      = k1 * c - k2 * sn;
    k[j + 16] = k2 * c + k1 * sn;
}

// ---------------------------------------------------------------------------
// Flash attention, fp32. Block = one (b, h, q-tile of 64). 256 threads.
// Q,K stored transposed in smem [d][row]; V row-major; P staged in smem.
// Thread (ty,tx): S microtile rows ty*4..+3, cols tx*4..+3;
//                 O microtile rows ty*4..+3, cols {tx*4..+3, 64+tx*4..+3}.
// ---------------------------------------------------------------------------
#define BQ 64
#define BK 64
#define FA_SMEM ((HS * BQ + HS * BK + BK * HS + BQ * BK) * 4)  // 114688 bytes

__global__ __launch_bounds__(256) void flash_attn()
{
    extern __shared__ float smem[];
    float* Qt = smem;                 // [HS][BQ]
    float* Kt = Qt + HS * BQ;         // [HS][BK]
    float* Vs = Kt + HS * BK;         // [BK][HS]
    float* Ps = Vs + BK * HS;         // [BQ][BK]

    const int qt = blockIdx.x;
    const int h  = blockIdx.y;
    const int b  = blockIdx.z;
    const int tid = threadIdx.x;
    const int ty = tid >> 4;          // 0..15
    const int tx = tid & 15;          // 0..15
    const int r0 = ty * 4;
    const int c0 = tx * 4;

    const int dd = (tid & 31) * 4;    // 0..124
    const int rr = tid >> 5;          // 0..7
    const size_t rowstride = (size_t)(3 * HS) * H;  // 6144 floats per seq row

    // ---- Load Q tile (scaled by 1/sqrt(HS)), transposed into Qt ----
    const size_t qrow0 = (size_t)(b * S_LEN + qt * BQ);
#pragma unroll
    for (int i = 0; i < 8; i++) {
        int r = rr + i * 8;
        const float* src = g_qkv + (qrow0 + r) * rowstride + (size_t)h * (3 * HS) + dd;
        float4 v = *(const float4*)src;
        Qt[(dd + 0) * BQ + r] = v.x * SCALE;
        Qt[(dd + 1) * BQ + r] = v.y * SCALE;
        Qt[(dd + 2) * BQ + r] = v.z * SCALE;
        Qt[(dd + 3) * BQ + r] = v.w * SCALE;
    }

    float m_run[4], l_run[4], o[4][8];
#pragma unroll
    for (int i = 0; i < 4; i++) {
        m_run[i] = -1e30f;
        l_run[i] = 0.0f;
#pragma unroll
        for (int cc = 0; cc < 8; cc++) o[i][cc] = 0.0f;
    }

    for (int kt = 0; kt < S_LEN / BK; kt++) {
        __syncthreads();  // previous iteration done reading Kt/Vs/Ps; Qt store also fenced (kt==0)

        // ---- Load K (transposed) and V tiles ----
        const size_t krow0 = (size_t)(b * S_LEN + kt * BK);
#pragma unroll
        for (int i = 0; i < 8; i++) {
            int r = rr + i * 8;
            const float* kp = g_qkv + (krow0 + r) * rowstride + (size_t)h * (3 * HS) + HS + dd;
            float4 kv4 = *(const float4*)kp;
            Kt[(dd + 0) * BK + r] = kv4.x;
            Kt[(dd + 1) * BK + r] = kv4.y;
            Kt[(dd + 2) * BK + r] = kv4.z;
            Kt[(dd + 3) * BK + r] = kv4.w;
            float4 vv4 = *(const float4*)(kp + HS);
            *(float4*)&Vs[r * HS + dd] = vv4;
        }
        __syncthreads();

        // ---- S = Q @ K^T (scaled), 4x4 per thread ----
        float sacc[4][4];
#pragma unroll
        for (int i = 0; i < 4; i++)
#pragma unroll
            for (int j = 0; j < 4; j++) sacc[i][j] = 0.0f;

#pragma unroll 8
        for (int d = 0; d < HS; d++) {
            float4 qv = *(const float4*)&Qt[d * BQ + r0];
            float4 kv = *(const float4*)&Kt[d * BK + c0];
            float qa[4] = {qv.x, qv.y, qv.z, qv.w};
            float ka[4] = {kv.x, kv.y, kv.z, kv.w};
#pragma unroll
            for (int i = 0; i < 4; i++)
#pragma unroll
                for (int j = 0; j < 4; j++)
                    sacc[i][j] += qa[i] * ka[j];
        }

        // ---- Online softmax (per row, reduce across the 16 tx lanes) ----
#pragma unroll
        for (int i = 0; i < 4; i++) {
            float mx = fmaxf(fmaxf(sacc[i][0], sacc[i][1]),
                             fmaxf(sacc[i][2], sacc[i][3]));
#pragma unroll
            for (int off = 8; off; off >>= 1)
                mx = fmaxf(mx, __shfl_xor_sync(0xffffffffu, mx, off));
            float mnew = fmaxf(m_run[i], mx);
            float alpha = expf(m_run[i] - mnew);
            float rsum = 0.0f;
#pragma unroll
            for (int j = 0; j < 4; j++) {
                float pw = expf(sacc[i][j] - mnew);
                Ps[(r0 + i) * BK + c0 + j] = pw;
                rsum += pw;
            }
#pragma unroll
            for (int off = 8; off; off >>= 1)
                rsum += __shfl_xor_sync(0xffffffffu, rsum, off);
            l_run[i] = l_run[i] * alpha + rsum;
            m_run[i] = mnew;
#pragma unroll
            for (int cc = 0; cc < 8; cc++) o[i][cc] *= alpha;
        }
        __syncthreads();

        // ---- O += P @ V ----
#pragma unroll 4
        for (int j = 0; j < BK; j++) {
            float p0 = Ps[(r0 + 0) * BK + j];
            float p1 = Ps[(r0 + 1) * BK + j];
            float p2 = Ps[(r0 + 2) * BK + j];
            float p3 = Ps[(r0 + 3) * BK + j];
            float4 v0 = *(const float4*)&Vs[j * HS + tx * 4];
            float4 v1 = *(const float4*)&Vs[j * HS + 64 + tx * 4];
            float va[8] = {v0.x, v0.y, v0.z, v0.w, v1.x, v1.y, v1.z, v1.w};
            float pp[4] = {p0, p1, p2, p3};
#pragma unroll
            for (int i = 0; i < 4; i++)
#pragma unroll
                for (int cc = 0; cc < 8; cc++)
                    o[i][cc] += pp[i] * va[cc];
        }
    }

    // ---- Normalize and write out ----
#pragma unroll
    for (int i = 0; i < 4; i++) {
        float inv = 1.0f / l_run[i];
        size_t orow = (qrow0 + r0 + i) * (size_t)(H * HS) + (size_t)h * HS;
        float4 w0 = make_float4(o[i][0] * inv, o[i][1] * inv, o[i][2] * inv, o[i][3] * inv);
        float4 w1 = make_float4(o[i][4] * inv, o[i][5] * inv, o[i][6] * inv, o[i][7] * inv);
        *(float4*)&g_attn[orow + tx * 4]      = w0;
        *(float4*)&g_attn[orow + 64 + tx * 4] = w1;
    }
}

// ---------------------------------------------------------------------------
// kernel_launch
// Inputs: hidden_states(f32), position_ids(i32), W_qkv(f32), b_qkv(f32),
//         W_dense(f32), b_dense(f32). Output: f32 (4096, 2048).
// ---------------------------------------------------------------------------
extern "C" void kernel_launch(void* const* d_in, const int* in_sizes, int n_in,
                              void* d_out, int out_size)
{
    const float* hidden = (const float*)d_in[0];
    const int*   pos    = (const int*)d_in[1];
    const float* Wqkv   = (const float*)d_in[2];
    const float* bqkv   = (const float*)d_in[3];
    const float* Wd     = (const float*)d_in[4];
    const float* bd     = (const float*)d_in[5];
    float* out = (float*)d_out;

    float* qkv_ptr  = nullptr;
    float* attn_ptr = nullptr;
    cudaGetSymbolAddress((void**)&qkv_ptr, g_qkv);
    cudaGetSymbolAddress((void**)&attn_ptr, g_attn);

    // 1) QKV projection: (4096,2048) @ (2048,6144) + bias
    sgemm_bias<<<dim3(N_QKV / 128, M_ROWS / 128), 256>>>(
        hidden, Wqkv, bqkv, qkv_ptr, M_ROWS, N_QKV, D_MODEL);

    // 2) RoPE in place on q,k
    rope_kernel<<<(B_SZ * S_LEN * H * (ROT / 2) + 255) / 256, 256>>>(pos);

    // 3) Flash attention
    cudaFuncSetAttribute(flash_attn, cudaFuncAttributeMaxDynamicSharedMemorySize, FA_SMEM);
    flash_attn<<<dim3(S_LEN / BQ, H, B_SZ), 256, FA_SMEM>>>();

    // 4) Dense: (4096,2048) @ (2048,2048) + bias
    sgemm_bias<<<dim3(D_MODEL / 128, M_ROWS / 128), 256>>>(
        attn_ptr, Wd, bd, out, M_ROWS, D_MODEL, D_MODEL);
}

// round 3
// speedup vs baseline: 2.2091x; 2.2091x over previous
#include <cuda_runtime.h>
#include <cuda_bf16.h>
#include <math.h>
#include <stdint.h>

#define H 16
#define HS 128
#define ROT 32
#define S_LEN 2048
#define B_SZ 2
#define D_MODEL 2048
#define N_QKV (3 * H * HS)          // 6144
#define M_ROWS (B_SZ * S_LEN)       // 4096
#define SCALE 0.08838834764831845f  // 1/sqrt(128)

// ---------------- scratch (__device__ globals) ------------------------------
__device__ float g_qkv[(size_t)M_ROWS * N_QKV];
__device__ float g_attn[(size_t)M_ROWS * (H * HS)];
__device__ uint32_t g_Ahi[(size_t)M_ROWS * D_MODEL / 2];
__device__ uint32_t g_Alo[(size_t)M_ROWS * D_MODEL / 2];
__device__ __nv_bfloat16 g_Whi[(size_t)N_QKV * D_MODEL];
__device__ __nv_bfloat16 g_Wlo[(size_t)N_QKV * D_MODEL];
__device__ __nv_bfloat16 g_DHhi[(size_t)D_MODEL * D_MODEL];
__device__ __nv_bfloat16 g_DHlo[(size_t)D_MODEL * D_MODEL];
__device__ uint32_t g_Phi[(size_t)M_ROWS * D_MODEL / 2];
__device__ uint32_t g_Plo[(size_t)M_ROWS * D_MODEL / 2];
// attention operand buffers (packed bf16x2, hi/lo)
__device__ uint32_t g_Qh[(size_t)B_SZ * H * S_LEN * (HS / 2)];
__device__ uint32_t g_Ql[(size_t)B_SZ * H * S_LEN * (HS / 2)];
__device__ uint32_t g_Kh[(size_t)B_SZ * H * S_LEN * (HS / 2)];
__device__ uint32_t g_Kl[(size_t)B_SZ * H * S_LEN * (HS / 2)];
__device__ uint32_t g_Vh[(size_t)B_SZ * H * HS * (S_LEN / 2)];
__device__ uint32_t g_Vl[(size_t)B_SZ * H * HS * (S_LEN / 2)];

// ---------------- helpers ----------------------------------------------------
__device__ __forceinline__ void split2(float x, float y, uint32_t& hi, uint32_t& lo)
{
    __nv_bfloat162 h = __floats2bfloat162_rn(x, y);
    float rx = x - __bfloat162float(h.x);
    float ry = y - __bfloat162float(h.y);
    __nv_bfloat162 l = __floats2bfloat162_rn(rx, ry);
    hi = *reinterpret_cast<uint32_t*>(&h);
    lo = *reinterpret_cast<uint32_t*>(&l);
}

__device__ __forceinline__ void mma16816(float* c, const uint32_t* a, const uint32_t* b)
{
    asm volatile(
        "mma.sync.aligned.m16n8k16.row.col.f32.bf16.bf16.f32 "
        "{%0,%1,%2,%3}, {%4,%5,%6,%7}, {%8,%9}, {%0,%1,%2,%3};"
        : "+f"(c[0]), "+f"(c[1]), "+f"(c[2]), "+f"(c[3])
        : "r"(a[0]), "r"(a[1]), "r"(a[2]), "r"(a[3]), "r"(b[0]), "r"(b[1]));
}

// ---------------- fp32 -> packed bf16x2 hi/lo (A operands) -------------------
__global__ void split_convert(const float* __restrict__ x,
                              uint32_t* __restrict__ hi,
                              uint32_t* __restrict__ lo, int n4)
{
    int i = blockIdx.x * blockDim.x + threadIdx.x;
    if (i >= n4) return;
    float4 v = ((const float4*)x)[i];
    uint32_t h0, l0, h1, l1;
    split2(v.x, v.y, h0, l0);
    split2(v.z, v.w, h1, l1);
    hi[i * 2]     = h0;
    hi[i * 2 + 1] = h1;
    lo[i * 2]     = l0;
    lo[i * 2 + 1] = l1;
}

// ---------------- W[K][N] f32 -> W^T[N][K] bf16 hi/lo ------------------------
__global__ void transpose_split(const float* __restrict__ W,
                                __nv_bfloat16* __restrict__ Thi,
                                __nv_bfloat16* __restrict__ Tlo, int K, int N)
{
    __shared__ float t[32][33];
    int n0 = blockIdx.x * 32, k0 = blockIdx.y * 32;
    int tx = threadIdx.x, ty = threadIdx.y;
#pragma unroll
    for (int i = 0; i < 32; i += 8)
        t[ty + i][tx] = W[(size_t)(k0 + ty + i) * N + n0 + tx];
    __syncthreads();
#pragma unroll
    for (int i = 0; i < 32; i += 8) {
        float x = t[tx][ty + i];
        __nv_bfloat16 h = __float2bfloat16_rn(x);
        __nv_bfloat16 l = __float2bfloat16_rn(x - __bfloat162float(h));
        size_t o = (size_t)(n0 + ty + i) * K + k0 + tx;
        Thi[o] = h;
        Tlo[o] = l;
    }
}

// ---------------- HMMA split-bf16 GEMM ---------------------------------------
// C[M,N] = A @ B^T + bias. A packed [M][K/2] u32 hi/lo; B^T packed [N][K/2].
// Block 128x128, 8 warps (2x4), each warp 64x32. K-chunk 64.
#define GSTR 36
#define GEMM_SMEM (4 * 128 * GSTR * 4)   // 73728 bytes

__global__ __launch_bounds__(256, 1) void gemm_mma(
    const uint32_t* __restrict__ Ah, const uint32_t* __restrict__ Al,
    const uint32_t* __restrict__ Bh, const uint32_t* __restrict__ Bl,
    const float* __restrict__ bias, float* __restrict__ C,
    int M, int N, int K)
{
    extern __shared__ uint32_t sm[];
    uint32_t* sAh = sm;
    uint32_t* sAl = sm + 128 * GSTR;
    uint32_t* sBh = sm + 2 * 128 * GSTR;
    uint32_t* sBl = sm + 3 * 128 * GSTR;

    const int tid = threadIdx.x;
    const int w = tid >> 5, lane = tid & 31;
    const int g = lane >> 2, tig = lane & 3;
    const int wm = (w >> 2) * 64, wn = (w & 3) * 32;
    const int m0 = blockIdx.y * 128, n0 = blockIdx.x * 128;
    const int K2 = K >> 1;

    float acc[4][4][4];
#pragma unroll
    for (int i = 0; i < 4; i++)
#pragma unroll
        for (int j = 0; j < 4; j++)
#pragma unroll
            for (int k = 0; k < 4; k++) acc[i][j][k] = 0.0f;

    const int NCH = K / 64;
    for (int c = 0; c < NCH; c++) {
        __syncthreads();
#pragma unroll
        for (int i = 0; i < 16; i++) {
            int idx = tid + i * 256;
            int row = idx >> 5, wd = idx & 31;
            size_t ga = (size_t)(m0 + row) * K2 + c * 32 + wd;
            size_t gb = (size_t)(n0 + row) * K2 + c * 32 + wd;
            sAh[row * GSTR + wd] = Ah[ga];
            sAl[row * GSTR + wd] = Al[ga];
            sBh[row * GSTR + wd] = Bh[gb];
            sBl[row * GSTR + wd] = Bl[gb];
        }
        __syncthreads();

#pragma unroll
        for (int ks = 0; ks < 4; ks++) {
            uint32_t ah[4][4], al[4][4], bh_[4][2], bl_[4][2];
#pragma unroll
            for (int mt = 0; mt < 4; mt++) {
                int base = (wm + 16 * mt + g) * GSTR + ks * 8 + tig;
                ah[mt][0] = sAh[base];
                ah[mt][1] = sAh[base + 8 * GSTR];
                ah[mt][2] = sAh[base + 4];
                ah[mt][3] = sAh[base + 8 * GSTR + 4];
                al[mt][0] = sAl[base];
                al[mt][1] = sAl[base + 8 * GSTR];
                al[mt][2] = sAl[base + 4];
                al[mt][3] = sAl[base + 8 * GSTR + 4];
            }
#pragma unroll
            for (int nt = 0; nt < 4; nt++) {
                int bb = (wn + 8 * nt + g) * GSTR + ks * 8 + tig;
                bh_[nt][0] = sBh[bb];
                bh_[nt][1] = sBh[bb + 4];
                bl_[nt][0] = sBl[bb];
                bl_[nt][1] = sBl[bb + 4];
            }
#pragma unroll
            for (int mt = 0; mt < 4; mt++)
#pragma unroll
                for (int nt = 0; nt < 4; nt++) {
                    mma16816(acc[mt][nt], ah[mt], bh_[nt]);
                    mma16816(acc[mt][nt], ah[mt], bl_[nt]);
                    mma16816(acc[mt][nt], al[mt], bh_[nt]);
                }
        }
    }

#pragma unroll
    for (int mt = 0; mt < 4; mt++)
#pragma unroll
        for (int nt = 0; nt < 4; nt++) {
            int row = m0 + wm + 16 * mt + g;
            int col = n0 + wn + 8 * nt + 2 * tig;
            float2 bv = *(const float2*)(bias + col);
            float2 o0 = make_float2(acc[mt][nt][0] + bv.x, acc[mt][nt][1] + bv.y);
            float2 o1 = make_float2(acc[mt][nt][2] + bv.x, acc[mt][nt][3] + bv.y);
            *(float2*)&C[(size_t)row * N + col]       = o0;
            *(float2*)&C[(size_t)(row + 8) * N + col] = o1;
        }
}

// ---------------- RoPE -------------------------------------------------------
__global__ void rope_kernel(const int* __restrict__ pos_ids)
{
    int idx = blockIdx.x * blockDim.x + threadIdx.x;
    const int total = B_SZ * S_LEN * H * (ROT / 2);
    if (idx >= total) return;

    int j = idx & 15;
    int t = idx >> 4;
    int h = t % H;  t /= H;
    int s = t % S_LEN;
    int b = t / S_LEN;

    int p = pos_ids[b * S_LEN + s];
    double f = pow(10000.0, -(double)(2 * j) / (double)ROT);
    double ang = (double)p * f;
    float c  = (float)cos(ang);
    float sn = (float)sin(ang);

    size_t base = ((size_t)(b * S_LEN + s) * H + h) * (size_t)(3 * HS);
    float* q = g_qkv + base;
    float q1 = q[j], q2 = q[j + 16];
    q[j]      = q1 * c - q2 * sn;
    q[j + 16] = q2 * c + q1 * sn;

    float* k = g_qkv + base + HS;
    float k1 = k[j], k2 = k[j + 16];
    k[j]      = k1 * c - k2 * sn;
    k[j + 16] = k2 * c + k1 * sn;
}

// ---------------- Q/K pre-convert to packed split bf16 -----------------------
// Qp/Kp layout: [(b*H+h)*S + s][HS/2] u32 (pairs along head dim). Q pre-scaled.
__global__ void qk_conv()
{
    int idx = blockIdx.x * blockDim.x + threadIdx.x;   // < 4096*16*64
    int j = idx & 63;
    int h = (idx >> 6) & 15;
    int r = idx >> 10;                                  // b*S + s
    const float* src = g_qkv + (size_t)r * N_QKV + h * (3 * HS);
    float2 q = *(const float2*)(src + 2 * j);
    float2 k = *(const float2*)(src + HS + 2 * j);
    uint32_t qh, ql, kh, kl;
    split2(q.x * SCALE, q.y * SCALE, qh, ql);
    split2(k.x, k.y, kh, kl);
    int bh = (r >> 11) * H + h;
    size_t oi = ((size_t)bh * S_LEN + (r & 2047)) * 64 + j;
    g_Qh[oi] = qh;
    g_Ql[oi] = ql;
    g_Kh[oi] = kh;
    g_Kl[oi] = kl;
}

// ---------------- V pre-convert: transpose into [bh][d][S/2] pairs -----------
__global__ __launch_bounds__(256) void v_conv()
{
    __shared__ float ts[64 * 133];
    const int s0 = blockIdx.x * 64;
    const int h  = blockIdx.y;
    const int b  = blockIdx.z;
    const int tid = threadIdx.x;

#pragma unroll
    for (int it = 0; it < 8; it++) {
        int f = tid + it * 256;        // 2048 float4
        int row = f >> 5, c4 = f & 31;
        float4 v = *(const float4*)(g_qkv + (size_t)(b * S_LEN + s0 + row) * N_QKV
                                    + h * (3 * HS) + 2 * HS + c4 * 4);
        ts[row * 133 + c4 * 4 + 0] = v.x;
        ts[row * 133 + c4 * 4 + 1] = v.y;
        ts[row * 133 + c4 * 4 + 2] = v.z;
        ts[row * 133 + c4 * 4 + 3] = v.w;
    }
    __syncthreads();

    const size_t obase = (size_t)(b * H + h) * HS * (S_LEN / 2);
#pragma unroll
    for (int it = 0; it < 16; it++) {
        int o = tid + it * 256;        // 4096
        int d = o >> 5, j = o & 31;
        float v0 = ts[(2 * j) * 133 + d];
        float v1 = ts[(2 * j + 1) * 133 + d];
        uint32_t vh, vl;
        split2(v0, v1, vh, vl);
        size_t oi = obase + (size_t)d * (S_LEN / 2) + (s0 >> 1) + j;
        g_Vh[oi] = vh;
        g_Vl[oi] = vl;
    }
}

// ---------------- flash attention with HMMA split-bf16 -----------------------
// Block: (b, h, 64 q-rows), 128 threads (4 warps x 16 rows). BK=64.
#define QSTR 68
#define VSTR 36
#define FA_SMEM ((4 * 64 * QSTR + 2 * 128 * VSTR) * 4)   // 106496 bytes

__global__ __launch_bounds__(128, 2) void flash_mma()
{
    extern __shared__ uint32_t fsm[];
    uint32_t* sQh = fsm;
    uint32_t* sQl = fsm + 64 * QSTR;
    uint32_t* sKh = fsm + 2 * 64 * QSTR;
    uint32_t* sKl = fsm + 3 * 64 * QSTR;
    uint32_t* sVh = fsm + 4 * 64 * QSTR;
    uint32_t* sVl = fsm + 4 * 64 * QSTR + 128 * VSTR;

    const int qt = blockIdx.x, h = blockIdx.y, b = blockIdx.z;
    const int tid = threadIdx.x;
    const int w = tid >> 5, lane = tid & 31;
    const int g = lane >> 2, tig = lane & 3;
    const int r0 = w * 16;
    const int bh = b * H + h;

    // load Q tile (rows qt*64..+63)
    const size_t qbase = ((size_t)bh * S_LEN + qt * 64) * 64;
#pragma unroll
    for (int i = 0; i < 32; i++) {
        int idx = tid + i * 128;       // 4096
        int row = idx >> 6, wd = idx & 63;
        sQh[row * QSTR + wd] = g_Qh[qbase + idx];
        sQl[row * QSTR + wd] = g_Ql[qbase + idx];
    }

    float o[16][4];
#pragma unroll
    for (int i = 0; i < 16; i++)
#pragma unroll
        for (int k = 0; k < 4; k++) o[i][k] = 0.0f;
    float m0 = -1e30f, m1 = -1e30f, l0 = 0.0f, l1 = 0.0f;

    for (int kt = 0; kt < S_LEN / 64; kt++) {
        __syncthreads();
        // K tile
        const size_t kbase = ((size_t)bh * S_LEN + kt * 64) * 64;
        const size_t vbase = (size_t)bh * HS * (S_LEN / 2) + kt * 32;
#pragma unroll
        for (int i = 0; i < 32; i++) {
            int idx = tid + i * 128;
            int row = idx >> 6, wd = idx & 63;
            sKh[row * QSTR + wd] = g_Kh[kbase + idx];
            sKl[row * QSTR + wd] = g_Kl[kbase + idx];
            int d = idx >> 5, j = idx & 31;
            sVh[d * VSTR + j] = g_Vh[vbase + (size_t)d * (S_LEN / 2) + j];
            sVl[d * VSTR + j] = g_Vl[vbase + (size_t)d * (S_LEN / 2) + j];
        }
        __syncthreads();

        // S = Q @ K^T  (split bf16, fp32 accum)
        float sc[8][4];
#pragma unroll
        for (int i = 0; i < 8; i++)
#pragma unroll
            for (int k = 0; k < 4; k++) sc[i][k] = 0.0f;

#pragma unroll
        for (int ds = 0; ds < 8; ds++) {
            int abase = (r0 + g) * QSTR + ds * 8 + tig;
            uint32_t ah[4] = { sQh[abase], sQh[abase + 8 * QSTR],
                               sQh[abase + 4], sQh[abase + 8 * QSTR + 4] };
            uint32_t al[4] = { sQl[abase], sQl[abase + 8 * QSTR],
                               sQl[abase + 4], sQl[abase + 8 * QSTR + 4] };
#pragma unroll
            for (int nt = 0; nt < 8; nt++) {
                int bb = (nt * 8 + g) * QSTR + ds * 8 + tig;
                uint32_t bkh[2] = { sKh[bb], sKh[bb + 4] };
                uint32_t bkl[2] = { sKl[bb], sKl[bb + 4] };
                mma16816(sc[nt], ah, bkh);
                mma16816(sc[nt], ah, bkl);
                mma16816(sc[nt], al, bkh);
            }
        }

        // online softmax (rows g and g+8 of this warp's 16-row strip)
        float mx0 = -1e30f, mx1 = -1e30f;
#pragma unroll
        for (int nt = 0; nt < 8; nt++) {
            mx0 = fmaxf(mx0, fmaxf(sc[nt][0], sc[nt][1]));
            mx1 = fmaxf(mx1, fmaxf(sc[nt][2], sc[nt][3]));
        }
        mx0 = fmaxf(mx0, __shfl_xor_sync(0xffffffffu, mx0, 1));
        mx0 = fmaxf(mx0, __shfl_xor_sync(0xffffffffu, mx0, 2));
        mx1 = fmaxf(mx1, __shfl_xor_sync(0xffffffffu, mx1, 1));
        mx1 = fmaxf(mx1, __shfl_xor_sync(0xffffffffu, mx1, 2));

        float mn0 = fmaxf(m0, mx0);
        float mn1 = fmaxf(m1, mx1);
        float a0 = __expf(m0 - mn0);
        float a1 = __expf(m1 - mn1);
        m0 = mn0;
        m1 = mn1;
        float add0 = 0.0f, add1 = 0.0f;
#pragma unroll
        for (int nt = 0; nt < 8; nt++) {
            sc[nt][0] = __expf(sc[nt][0] - mn0);
            sc[nt][1] = __expf(sc[nt][1] - mn0);
            sc[nt][2] = __expf(sc[nt][2] - mn1);
            sc[nt][3] = __expf(sc[nt][3] - mn1);
            add0 += sc[nt][0] + sc[nt][1];
            add1 += sc[nt][2] + sc[nt][3];
        }
        l0 = l0 * a0 + add0;
        l1 = l1 * a1 + add1;
#pragma unroll
        for (int nt = 0; nt < 16; nt++) {
            o[nt][0] *= a0;
            o[nt][1] *= a0;
            o[nt][2] *= a1;
            o[nt][3] *= a1;
        }

        // O += P @ V  (P from S-fragments, split)
#pragma unroll
        for (int kk = 0; kk < 4; kk++) {
            uint32_t ph[4], pl[4];
            split2(sc[2 * kk][0],     sc[2 * kk][1],     ph[0], pl[0]);
            split2(sc[2 * kk][2],     sc[2 * kk][3],     ph[1], pl[1]);
            split2(sc[2 * kk + 1][0], sc[2 * kk + 1][1], ph[2], pl[2]);
            split2(sc[2 * kk + 1][2], sc[2 * kk + 1][3], ph[3], pl[3]);
#pragma unroll
            for (int nt = 0; nt < 16; nt++) {
                int bb = (nt * 8 + g) * VSTR + kk * 8 + tig;
                uint32_t bvh[2] = { sVh[bb], sVh[bb + 4] };
                uint32_t bvl[2] = { sVl[bb], sVl[bb + 4] };
                mma16816(o[nt], ph, bvh);
                mma16816(o[nt], ph, bvl);
                mma16816(o[nt], pl, bvh);
            }
        }
    }

    // final row-sum reduction + store
    l0 += __shfl_xor_sync(0xffffffffu, l0, 1);
    l0 += __shfl_xor_sync(0xffffffffu, l0, 2);
    l1 += __shfl_xor_sync(0xffffffffu, l1, 1);
    l1 += __shfl_xor_sync(0xffffffffu, l1, 2);
    float inv0 = 1.0f / l0;
    float inv1 = 1.0f / l1;

    int row = b * S_LEN + qt * 64 + r0 + g;
#pragma unroll
    for (int nt = 0; nt < 16; nt++) {
        int col = h * HS + nt * 8 + 2 * tig;
        float2 o0 = make_float2(o[nt][0] * inv0, o[nt][1] * inv0);
        float2 o1 = make_float2(o[nt][2] * inv1, o[nt][3] * inv1);
        *(float2*)&g_attn[(size_t)row * (H * HS) + col]       = o0;
        *(float2*)&g_attn[(size_t)(row + 8) * (H * HS) + col] = o1;
    }
}

// ---------------- kernel_launch ---------------------------------------------
extern "C" void kernel_launch(void* const* d_in, const int* in_sizes, int n_in,
                              void* d_out, int out_size)
{
    const float* hidden = (const float*)d_in[0];
    const int*   pos    = (const int*)d_in[1];
    const float* Wqkv   = (const float*)d_in[2];
    const float* bqkv   = (const float*)d_in[3];
    const float* Wd     = (const float*)d_in[4];
    const float* bd     = (const float*)d_in[5];
    float* out = (float*)d_out;

    float *qkv_p, *attn_p;
    uint32_t *Ahi, *Alo, *Phi, *Plo;
    __nv_bfloat16 *Whi, *Wlo, *Dhi, *Dlo;
    cudaGetSymbolAddress((void**)&qkv_p,  g_qkv);
    cudaGetSymbolAddress((void**)&attn_p, g_attn);
    cudaGetSymbolAddress((void**)&Ahi, g_Ahi);
    cudaGetSymbolAddress((void**)&Alo, g_Alo);
    cudaGetSymbolAddress((void**)&Whi, g_Whi);
    cudaGetSymbolAddress((void**)&Wlo, g_Wlo);
    cudaGetSymbolAddress((void**)&Dhi, g_DHhi);
    cudaGetSymbolAddress((void**)&Dlo, g_DHlo);
    cudaGetSymbolAddress((void**)&Phi, g_Phi);
    cudaGetSymbolAddress((void**)&Plo, g_Plo);

    cudaFuncSetAttribute(gemm_mma, cudaFuncAttributeMaxDynamicSharedMemorySize, GEMM_SMEM);
    cudaFuncSetAttribute(flash_mma, cudaFuncAttributeMaxDynamicSharedMemorySize, FA_SMEM);

    const int n4 = (M_ROWS * D_MODEL) / 4;

    // 1) split hidden (packed pairs)
    split_convert<<<(n4 + 255) / 256, 256>>>(hidden, Ahi, Alo, n4);
    // 2) weight transposes + splits
    transpose_split<<<dim3(N_QKV / 32, D_MODEL / 32), dim3(32, 8)>>>(
        Wqkv, Whi, Wlo, D_MODEL, N_QKV);
    transpose_split<<<dim3(D_MODEL / 32, D_MODEL / 32), dim3(32, 8)>>>(
        Wd, Dhi, Dlo, D_MODEL, D_MODEL);
    // 3) QKV projection
    gemm_mma<<<dim3(N_QKV / 128, M_ROWS / 128), 256, GEMM_SMEM>>>(
        Ahi, Alo, (const uint32_t*)Whi, (const uint32_t*)Wlo,
        bqkv, qkv_p, M_ROWS, N_QKV, D_MODEL);
    // 4) RoPE
    rope_kernel<<<(B_SZ * S_LEN * H * (ROT / 2) + 255) / 256, 256>>>(pos);
    // 5) pre-convert attention operands
    qk_conv<<<(M_ROWS * H * 64) / 256, 256>>>();
    v_conv<<<dim3(S_LEN / 64, H, B_SZ), 256>>>();
    // 6) flash attention (HMMA)
    flash_mma<<<dim3(S_LEN / 64, H, B_SZ), 128, FA_SMEM>>>();
    // 7) split attention output
    split_convert<<<(n4 + 255) / 256, 256>>>(attn_p, Phi, Plo, n4);
    // 8) dense projection
    gemm_mma<<<dim3(D_MODEL / 128, M_ROWS / 128), 256, GEMM_SMEM>>>(
        Phi, Plo, (const uint32_t*)Dhi, (const uint32_t*)Dlo,
        bd, out, M_ROWS, D_MODEL, D_MODEL);
}

// round 4
// speedup vs baseline: 3.4835x; 1.5769x over previous
#include <cuda_runtime.h>
#include <cuda_bf16.h>
#include <math.h>
#include <stdint.h>

#define H 16
#define HS 128
#define ROT 32
#define S_LEN 2048
#define B_SZ 2
#define D_MODEL 2048
#define N_QKV 6144
#define M_ROWS 4096
#define SCALE 0.08838834764831845f  // 1/sqrt(128)

// ---------------- scratch (__device__ globals) ------------------------------
__device__ float g_qkv[(size_t)M_ROWS * N_QKV];
__device__ uint32_t g_Ahi[(size_t)M_ROWS * D_MODEL / 2];
__device__ uint32_t g_Alo[(size_t)M_ROWS * D_MODEL / 2];
__device__ __nv_bfloat16 g_Whi[(size_t)N_QKV * D_MODEL];
__device__ __nv_bfloat16 g_Wlo[(size_t)N_QKV * D_MODEL];
__device__ __nv_bfloat16 g_DHhi[(size_t)D_MODEL * D_MODEL];
__device__ __nv_bfloat16 g_DHlo[(size_t)D_MODEL * D_MODEL];
__device__ uint32_t g_Phi[(size_t)M_ROWS * D_MODEL / 2];
__device__ uint32_t g_Plo[(size_t)M_ROWS * D_MODEL / 2];
__device__ uint32_t g_Qh[(size_t)B_SZ * H * S_LEN * (HS / 2)];
__device__ uint32_t g_Ql[(size_t)B_SZ * H * S_LEN * (HS / 2)];
__device__ uint32_t g_Kh[(size_t)B_SZ * H * S_LEN * (HS / 2)];
__device__ uint32_t g_Kl[(size_t)B_SZ * H * S_LEN * (HS / 2)];
__device__ uint32_t g_Vh[(size_t)B_SZ * H * HS * (S_LEN / 2)];
__device__ uint32_t g_Vl[(size_t)B_SZ * H * HS * (S_LEN / 2)];
__device__ float g_cosT[S_LEN * 16];
__device__ float g_sinT[S_LEN * 16];

// ---------------- PTX helpers ------------------------------------------------
__device__ __forceinline__ uint32_t smem_u32(const void* p) {
    uint32_t a;
    asm("{ .reg .u64 t; cvta.to.shared.u64 t, %1; cvt.u32.u64 %0, t; }"
        : "=r"(a) : "l"(p));
    return a;
}
__device__ __forceinline__ void cp16(uint32_t dst, const void* src) {
    asm volatile("cp.async.cg.shared.global [%0], [%1], 16;" :: "r"(dst), "l"(src));
}
__device__ __forceinline__ void cp_commit() {
    asm volatile("cp.async.commit_group;" ::: "memory");
}
template <int N>
__device__ __forceinline__ void cp_wait() {
    asm volatile("cp.async.wait_group %0;" :: "n"(N) : "memory");
}
__device__ __forceinline__ void ldm4(uint32_t* d, uint32_t addr) {
    asm volatile("ldmatrix.sync.aligned.m8n8.x4.shared.b16 {%0,%1,%2,%3}, [%4];"
                 : "=r"(d[0]), "=r"(d[1]), "=r"(d[2]), "=r"(d[3]) : "r"(addr));
}
__device__ __forceinline__ void mma16816(float* c, const uint32_t* a, const uint32_t* b)
{
    asm volatile(
        "mma.sync.aligned.m16n8k16.row.col.f32.bf16.bf16.f32 "
        "{%0,%1,%2,%3}, {%4,%5,%6,%7}, {%8,%9}, {%0,%1,%2,%3};"
        : "+f"(c[0]), "+f"(c[1]), "+f"(c[2]), "+f"(c[3])
        : "r"(a[0]), "r"(a[1]), "r"(a[2]), "r"(a[3]), "r"(b[0]), "r"(b[1]));
}
__device__ __forceinline__ void split2(float x, float y, uint32_t& hi, uint32_t& lo)
{
    __nv_bfloat162 h = __floats2bfloat162_rn(x, y);
    float rx = x - __bfloat162float(h.x);
    float ry = y - __bfloat162float(h.y);
    __nv_bfloat162 l = __floats2bfloat162_rn(rx, ry);
    hi = *reinterpret_cast<uint32_t*>(&h);
    lo = *reinterpret_cast<uint32_t*>(&l);
}

// ---------------- small prep kernels -----------------------------------------
__global__ void split_convert(const float* __restrict__ x,
                              uint32_t* __restrict__ hi,
                              uint32_t* __restrict__ lo, int n4)
{
    int i = blockIdx.x * blockDim.x + threadIdx.x;
    if (i >= n4) return;
    float4 v = ((const float4*)x)[i];
    uint32_t h0, l0, h1, l1;
    split2(v.x, v.y, h0, l0);
    split2(v.z, v.w, h1, l1);
    hi[i * 2]     = h0;
    hi[i * 2 + 1] = h1;
    lo[i * 2]     = l0;
    lo[i * 2 + 1] = l1;
}

__global__ void transpose_split(const float* __restrict__ W,
                                __nv_bfloat16* __restrict__ Thi,
                                __nv_bfloat16* __restrict__ Tlo, int K, int N)
{
    __shared__ float t[32][33];
    int n0 = blockIdx.x * 32, k0 = blockIdx.y * 32;
    int tx = threadIdx.x, ty = threadIdx.y;
#pragma unroll
    for (int i = 0; i < 32; i += 8)
        t[ty + i][tx] = W[(size_t)(k0 + ty + i) * N + n0 + tx];
    __syncthreads();
#pragma unroll
    for (int i = 0; i < 32; i += 8) {
        float x = t[tx][ty + i];
        __nv_bfloat16 h = __float2bfloat16_rn(x);
        __nv_bfloat16 l = __float2bfloat16_rn(x - __bfloat162float(h));
        size_t o = (size_t)(n0 + ty + i) * K + k0 + tx;
        Thi[o] = h;
        Tlo[o] = l;
    }
}

__global__ void rope_table()
{
    int idx = blockIdx.x * blockDim.x + threadIdx.x;
    if (idx >= S_LEN * 16) return;
    int p = idx >> 4, i = idx & 15;
    double f = exp(-(double)(2 * i) / (double)ROT * log(10000.0));
    double a = (double)p * f;
    g_cosT[idx] = (float)cos(a);
    g_sinT[idx] = (float)sin(a);
}

// ---------------- qk_conv with fused RoPE ------------------------------------
__global__ void qk_conv(const int* __restrict__ pos)
{
    int idx = blockIdx.x * blockDim.x + threadIdx.x;  // M_ROWS*H*64
    int j = idx & 63;
    int h = (idx >> 6) & 15;
    int r = idx >> 10;
    const float* src = g_qkv + (size_t)r * N_QKV + h * (3 * HS);
    float q0, q1, k0, k1;

    if (j < 16) {
        int p = pos[r];
        const float* ct = g_cosT + p * 16;
        const float* st = g_sinT + p * 16;
        if (j < 8) {                       // dims 2j, 2j+1 in [0,16)
            int d0 = 2 * j, d1 = 2 * j + 1;
            float c0 = ct[d0], s0 = st[d0], c1 = ct[d1], s1 = st[d1];
            q0 = src[d0] * c0 - src[d0 + 16] * s0;
            q1 = src[d1] * c1 - src[d1 + 16] * s1;
            k0 = src[HS + d0] * c0 - src[HS + d0 + 16] * s0;
            k1 = src[HS + d1] * c1 - src[HS + d1 + 16] * s1;
        } else {                           // dims in [16,32)
            int d0 = 2 * j, d1 = 2 * j + 1;
            int i0 = d0 - 16, i1 = d1 - 16;
            float c0 = ct[i0], s0 = st[i0], c1 = ct[i1], s1 = st[i1];
            q0 = src[d0] * c0 + src[i0] * s0;
            q1 = src[d1] * c1 + src[i1] * s1;
            k0 = src[HS + d0] * c0 + src[HS + i0] * s0;
            k1 = src[HS + d1] * c1 + src[HS + i1] * s1;
        }
    } else {
        float2 q = *(const float2*)(src + 2 * j);
        float2 k = *(const float2*)(src + HS + 2 * j);
        q0 = q.x; q1 = q.y; k0 = k.x; k1 = k.y;
    }

    uint32_t qh, ql, kh, kl;
    split2(q0 * SCALE, q1 * SCALE, qh, ql);
    split2(k0, k1, kh, kl);
    int bh = (r >> 11) * H + h;
    size_t oi = ((size_t)bh * S_LEN + (r & 2047)) * 64 + j;
    g_Qh[oi] = qh;
    g_Ql[oi] = ql;
    g_Kh[oi] = kh;
    g_Kl[oi] = kl;
}

// ---------------- V transpose + split ----------------------------------------
__global__ __launch_bounds__(256) void v_conv()
{
    __shared__ float ts[64 * 133];
    const int s0 = blockIdx.x * 64;
    const int h  = blockIdx.y;
    const int b  = blockIdx.z;
    const int tid = threadIdx.x;

#pragma unroll
    for (int it = 0; it < 8; it++) {
        int f = tid + it * 256;
        int row = f >> 5, c4 = f & 31;
        float4 v = *(const float4*)(g_qkv + (size_t)(b * S_LEN + s0 + row) * N_QKV
                                    + h * (3 * HS) + 2 * HS + c4 * 4);
        ts[row * 133 + c4 * 4 + 0] = v.x;
        ts[row * 133 + c4 * 4 + 1] = v.y;
        ts[row * 133 + c4 * 4 + 2] = v.z;
        ts[row * 133 + c4 * 4 + 3] = v.w;
    }
    __syncthreads();

    const size_t obase = (size_t)(b * H + h) * HS * (S_LEN / 2);
#pragma unroll
    for (int it = 0; it < 16; it++) {
        int o = tid + it * 256;
        int d = o >> 5, j = o & 31;
        float v0 = ts[(2 * j) * 133 + d];
        float v1 = ts[(2 * j + 1) * 133 + d];
        uint32_t vh, vl;
        split2(v0, v1, vh, vl);
        size_t oi = obase + (size_t)d * (S_LEN / 2) + (s0 >> 1) + j;
        g_Vh[oi] = vh;
        g_Vl[oi] = vl;
    }
}

// ---------------- GEMM: cp.async 4-stage + ldmatrix --------------------------
// C[M,N] = A @ B^T + bias. Block 128x128, 8 warps (2x4), warp 64x32, KC=32.
// Stage 32KB: Ah@0, Al@8K, Bh@16K, Bl@24K. Row = 64B = 4 chunks of 16B.
#define GKC 32
#define GSTG 32768
#define GEMM_SMEM (4 * GSTG)

__device__ __forceinline__ uint32_t gswz(int row, int chunk) {
    return (uint32_t)(row * 64 + ((chunk ^ ((row >> 1) & 3)) << 4));
}

__global__ __launch_bounds__(256, 1) void gemm_mma(
    const uint32_t* __restrict__ Ah, const uint32_t* __restrict__ Al,
    const uint32_t* __restrict__ Bh, const uint32_t* __restrict__ Bl,
    const float* __restrict__ bias, float* __restrict__ C,
    int M, int N, int K)
{
    extern __shared__ uint32_t smg[];
    const uint32_t sb = smem_u32(smg);
    const int tid = threadIdx.x;
    const int w = tid >> 5, lane = tid & 31;
    const int g = lane >> 2, tig = lane & 3;
    const int r8 = lane & 7, mi = lane >> 3;
    const int wm = (w >> 2) * 64, wn = (w & 3) * 32;
    const int m0 = blockIdx.y * 128, n0 = blockIdx.x * 128;
    const int K2 = K >> 1;
    const int NCH = K / GKC;

    float acc[4][4][4];
#pragma unroll
    for (int i = 0; i < 4; i++)
#pragma unroll
        for (int j = 0; j < 4; j++)
#pragma unroll
            for (int k = 0; k < 4; k++) acc[i][j][k] = 0.0f;

    auto issue = [&](int c) {
        uint32_t st = sb + (c & 3) * GSTG;
        int kw = c * 16;
#pragma unroll
        for (int i = 0; i < 8; i++) {
            int idx = tid + i * 256;
            int arr = idx >> 9, rem = idx & 511;
            int row = rem >> 2, ch = rem & 3;
            const uint32_t* gp;
            if (arr == 0)      gp = Ah + (size_t)(m0 + row) * K2 + kw + ch * 4;
            else if (arr == 1) gp = Al + (size_t)(m0 + row) * K2 + kw + ch * 4;
            else if (arr == 2) gp = Bh + (size_t)(n0 + row) * K2 + kw + ch * 4;
            else               gp = Bl + (size_t)(n0 + row) * K2 + kw + ch * 4;
            cp16(st + arr * 8192 + gswz(row, ch), gp);
        }
        cp_commit();
    };

    issue(0); issue(1); issue(2);

    for (int c = 0; c < NCH; c++) {
        if (c + 3 < NCH) { issue(c + 3); cp_wait<3>(); }
        else             { cp_wait<0>(); }
        __syncthreads();
        uint32_t st = sb + (c & 3) * GSTG;

#pragma unroll
        for (int ks = 0; ks < 2; ks++) {
            uint32_t ahf[4][4], alf[4][4], bhf[4][2], blf[4][2];
#pragma unroll
            for (int mt = 0; mt < 4; mt++) {
                int row = wm + 16 * mt + ((mi & 1) << 3) + r8;
                int ch = 2 * ks + (mi >> 1);
                uint32_t sw = gswz(row, ch);
                ldm4(ahf[mt], st + sw);
                ldm4(alf[mt], st + 8192 + sw);
            }
#pragma unroll
            for (int j = 0; j < 2; j++) {
                int row = wn + 16 * j + ((mi >> 1) << 3) + r8;
                int ch = 2 * ks + (mi & 1);
                uint32_t sw = gswz(row, ch);
                uint32_t t4[4];
                ldm4(t4, st + 16384 + sw);
                bhf[2 * j][0] = t4[0]; bhf[2 * j][1] = t4[1];
                bhf[2 * j + 1][0] = t4[2]; bhf[2 * j + 1][1] = t4[3];
                ldm4(t4, st + 24576 + sw);
                blf[2 * j][0] = t4[0]; blf[2 * j][1] = t4[1];
                blf[2 * j + 1][0] = t4[2]; blf[2 * j + 1][1] = t4[3];
            }
#pragma unroll
            for (int mt = 0; mt < 4; mt++)
#pragma unroll
                for (int nt = 0; nt < 4; nt++) {
                    mma16816(acc[mt][nt], ahf[mt], bhf[nt]);
                    mma16816(acc[mt][nt], ahf[mt], blf[nt]);
                    mma16816(acc[mt][nt], alf[mt], bhf[nt]);
                }
        }
        __syncthreads();
    }

#pragma unroll
    for (int mt = 0; mt < 4; mt++)
#pragma unroll
        for (int nt = 0; nt < 4; nt++) {
            int row = m0 + wm + 16 * mt + g;
            int col = n0 + wn + 8 * nt + 2 * tig;
            float2 bv = *(const float2*)(bias + col);
            float2 o0 = make_float2(acc[mt][nt][0] + bv.x, acc[mt][nt][1] + bv.y);
            float2 o1 = make_float2(acc[mt][nt][2] + bv.x, acc[mt][nt][3] + bv.y);
            *(float2*)&C[(size_t)row * N + col]       = o0;
            *(float2*)&C[(size_t)(row + 8) * N + col] = o1;
        }
}

// ---------------- flash attention: cp.async 2-stage + ldmatrix ---------------
// Block: BQ=128, 256 threads (8 warps x 16 rows). BK=64.
// Stage 64KB: Kh@0, Kl@16K, Vh@32K, Vl@48K.
// K rows 64 x 256B (16 chunks); V rows 128 x 128B (8 chunks).
#define FSTG 65536
#define FA_SMEM (2 * FSTG)

__device__ __forceinline__ uint32_t kswz(int row, int chunk) {
    return (uint32_t)(row * 256 + ((chunk ^ (row & 7)) << 4));
}
__device__ __forceinline__ uint32_t vswz(int row, int chunk) {
    return (uint32_t)(row * 128 + ((chunk ^ (row & 7)) << 4));
}

__global__ __launch_bounds__(256, 1) void flash_mma()
{
    extern __shared__ uint32_t smf[];
    const uint32_t sb = smem_u32(smf);

    const int qt = blockIdx.x, h = blockIdx.y, b = blockIdx.z;
    const int tid = threadIdx.x;
    const int w = tid >> 5, lane = tid & 31;
    const int g = lane >> 2, tig = lane & 3;
    const int r8 = lane & 7, mi = lane >> 3;
    const int bh = b * H + h;

    // ---- hoist Q fragments (registers) ----
    const size_t qrow = (size_t)bh * S_LEN + qt * 128 + w * 16;
    const uint32_t* q0h = g_Qh + (qrow + g) * 64;
    const uint32_t* q8h = q0h + 8 * 64;
    const uint32_t* q0l = g_Ql + (qrow + g) * 64;
    const uint32_t* q8l = q0l + 8 * 64;
    uint32_t qh[8][4], ql[8][4];
#pragma unroll
    for (int ds = 0; ds < 8; ds++) {
        qh[ds][0] = q0h[ds * 8 + tig];
        qh[ds][1] = q8h[ds * 8 + tig];
        qh[ds][2] = q0h[ds * 8 + 4 + tig];
        qh[ds][3] = q8h[ds * 8 + 4 + tig];
        ql[ds][0] = q0l[ds * 8 + tig];
        ql[ds][1] = q8l[ds * 8 + tig];
        ql[ds][2] = q0l[ds * 8 + 4 + tig];
        ql[ds][3] = q8l[ds * 8 + 4 + tig];
    }

    auto issueKV = [&](int kt) {
        uint32_t st = sb + (kt & 1) * FSTG;
        const size_t kbase = ((size_t)bh * S_LEN + kt * 64) * 64;
        const size_t vbase = (size_t)bh * HS * (S_LEN / 2) + kt * 32;
#pragma unroll
        for (int i = 0; i < 8; i++) {
            int idx = tid + i * 256;
            int arr = idx >> 10, rem = idx & 1023;
            int row = rem >> 4, ch = rem & 15;
            const uint32_t* src = (arr ? g_Kl : g_Kh) + kbase + row * 64 + ch * 4;
            cp16(st + arr * 16384 + kswz(row, ch), src);
        }
#pragma unroll
        for (int i = 0; i < 8; i++) {
            int idx = tid + i * 256;
            int arr = idx >> 10, rem = idx & 1023;
            int row = rem >> 3, ch = rem & 7;
            const uint32_t* src = (arr ? g_Vl : g_Vh) + vbase
                                  + (size_t)row * (S_LEN / 2) + ch * 4;
            cp16(st + 32768 + arr * 16384 + vswz(row, ch), src);
        }
        cp_commit();
    };

    float o[16][4];
#pragma unroll
    for (int i = 0; i < 16; i++)
#pragma unroll
        for (int k = 0; k < 4; k++) o[i][k] = 0.0f;
    float m0 = -1e30f, m1 = -1e30f, l0 = 0.0f, l1 = 0.0f;

    issueKV(0);

    for (int kt = 0; kt < S_LEN / 64; kt++) {
        if (kt + 1 < S_LEN / 64) { issueKV(kt + 1); cp_wait<1>(); }
        else                     { cp_wait<0>(); }
        __syncthreads();
        uint32_t st = sb + (kt & 1) * FSTG;

        // ---- S = Q @ K^T ----
        float sc[8][4];
#pragma unroll
        for (int i = 0; i < 8; i++)
#pragma unroll
            for (int k = 0; k < 4; k++) sc[i][k] = 0.0f;

#pragma unroll
        for (int ds = 0; ds < 8; ds++) {
#pragma unroll
            for (int j = 0; j < 4; j++) {
                int row = 16 * j + ((mi >> 1) << 3) + r8;
                int ch = 2 * ds + (mi & 1);
                uint32_t sw = kswz(row, ch);
                uint32_t kh4[4], kl4[4];
                ldm4(kh4, st + sw);
                ldm4(kl4, st + 16384 + sw);
                mma16816(sc[2 * j],     qh[ds], kh4);
                mma16816(sc[2 * j],     qh[ds], kl4);
                mma16816(sc[2 * j],     ql[ds], kh4);
                mma16816(sc[2 * j + 1], qh[ds], kh4 + 2);
                mma16816(sc[2 * j + 1], qh[ds], kl4 + 2);
                mma16816(sc[2 * j + 1], ql[ds], kh4 + 2);
            }
        }

        // ---- online softmax ----
        float mx0 = -1e30f, mx1 = -1e30f;
#pragma unroll
        for (int nt = 0; nt < 8; nt++) {
            mx0 = fmaxf(mx0, fmaxf(sc[nt][0], sc[nt][1]));
            mx1 = fmaxf(mx1, fmaxf(sc[nt][2], sc[nt][3]));
        }
        mx0 = fmaxf(mx0, __shfl_xor_sync(0xffffffffu, mx0, 1));
        mx0 = fmaxf(mx0, __shfl_xor_sync(0xffffffffu, mx0, 2));
        mx1 = fmaxf(mx1, __shfl_xor_sync(0xffffffffu, mx1, 1));
        mx1 = fmaxf(mx1, __shfl_xor_sync(0xffffffffu, mx1, 2));

        float mn0 = fmaxf(m0, mx0);
        float mn1 = fmaxf(m1, mx1);
        float a0 = __expf(m0 - mn0);
        float a1 = __expf(m1 - mn1);
        m0 = mn0;
        m1 = mn1;
        float add0 = 0.0f, add1 = 0.0f;
#pragma unroll
        for (int nt = 0; nt < 8; nt++) {
            sc[nt][0] = __expf(sc[nt][0] - mn0);
            sc[nt][1] = __expf(sc[nt][1] - mn0);
            sc[nt][2] = __expf(sc[nt][2] - mn1);
            sc[nt][3] = __expf(sc[nt][3] - mn1);
            add0 += sc[nt][0] + sc[nt][1];
            add1 += sc[nt][2] + sc[nt][3];
        }
        l0 = l0 * a0 + add0;
        l1 = l1 * a1 + add1;
#pragma unroll
        for (int nt = 0; nt < 16; nt++) {
            o[nt][0] *= a0;
            o[nt][1] *= a0;
            o[nt][2] *= a1;
            o[nt][3] *= a1;
        }

        // ---- O += P @ V ----
#pragma unroll
        for (int kk = 0; kk < 4; kk++) {
            uint32_t ph[4], pl[4];
            split2(sc[2 * kk][0],     sc[2 * kk][1],     ph[0], pl[0]);
            split2(sc[2 * kk][2],     sc[2 * kk][3],     ph[1], pl[1]);
            split2(sc[2 * kk + 1][0], sc[2 * kk + 1][1], ph[2], pl[2]);
            split2(sc[2 * kk + 1][2], sc[2 * kk + 1][3], ph[3], pl[3]);
#pragma unroll
            for (int j = 0; j < 8; j++) {
                int row = 16 * j + ((mi >> 1) << 3) + r8;
                int ch = 2 * kk + (mi & 1);
                uint32_t sw = vswz(row, ch);
                uint32_t vh4[4], vl4[4];
                ldm4(vh4, st + 32768 + sw);
                ldm4(vl4, st + 49152 + sw);
                mma16816(o[2 * j],     ph, vh4);
                mma16816(o[2 * j],     ph, vl4);
                mma16816(o[2 * j],     pl, vh4);
                mma16816(o[2 * j + 1], ph, vh4 + 2);
                mma16816(o[2 * j + 1], ph, vl4 + 2);
                mma16816(o[2 * j + 1], pl, vh4 + 2);
            }
        }
        __syncthreads();
    }

    // ---- normalize, split, store directly to g_Phi/g_Plo ----
    l0 += __shfl_xor_sync(0xffffffffu, l0, 1);
    l0 += __shfl_xor_sync(0xffffffffu, l0, 2);
    l1 += __shfl_xor_sync(0xffffffffu, l1, 1);
    l1 += __shfl_xor_sync(0xffffffffu, l1, 2);
    float inv0 = 1.0f / l0;
    float inv1 = 1.0f / l1;

    size_t row0 = (size_t)(b * S_LEN + qt * 128 + w * 16 + g);
#pragma unroll
    for (int nt = 0; nt < 16; nt++) {
        size_t wd = h * 64 + nt * 4 + tig;
        uint32_t hi, lo;
        split2(o[nt][0] * inv0, o[nt][1] * inv0, hi, lo);
        g_Phi[row0 * 1024 + wd] = hi;
        g_Plo[row0 * 1024 + wd] = lo;
        split2(o[nt][2] * inv1, o[nt][3] * inv1, hi, lo);
        g_Phi[(row0 + 8) * 1024 + wd] = hi;
        g_Plo[(row0 + 8) * 1024 + wd] = lo;
    }
}

// ---------------- kernel_launch ---------------------------------------------
extern "C" void kernel_launch(void* const* d_in, const int* in_sizes, int n_in,
                              void* d_out, int out_size)
{
    const float* hidden = (const float*)d_in[0];
    const int*   pos    = (const int*)d_in[1];
    const float* Wqkv   = (const float*)d_in[2];
    const float* bqkv   = (const float*)d_in[3];
    const float* Wd     = (const float*)d_in[4];
    const float* bd     = (const float*)d_in[5];
    float* out = (float*)d_out;

    float* qkv_p;
    uint32_t *Ahi, *Alo, *Phi, *Plo;
    __nv_bfloat16 *Whi, *Wlo, *Dhi, *Dlo;
    cudaGetSymbolAddress((void**)&qkv_p, g_qkv);
    cudaGetSymbolAddress((void**)&Ahi, g_Ahi);
    cudaGetSymbolAddress((void**)&Alo, g_Alo);
    cudaGetSymbolAddress((void**)&Whi, g_Whi);
    cudaGetSymbolAddress((void**)&Wlo, g_Wlo);
    cudaGetSymbolAddress((void**)&Dhi, g_DHhi);
    cudaGetSymbolAddress((void**)&Dlo, g_DHlo);
    cudaGetSymbolAddress((void**)&Phi, g_Phi);
    cudaGetSymbolAddress((void**)&Plo, g_Plo);

    cudaFuncSetAttribute(gemm_mma, cudaFuncAttributeMaxDynamicSharedMemorySize, GEMM_SMEM);
    cudaFuncSetAttribute(flash_mma, cudaFuncAttributeMaxDynamicSharedMemorySize, FA_SMEM);

    const int n4 = (M_ROWS * D_MODEL) / 4;

    split_convert<<<(n4 + 255) / 256, 256>>>(hidden, Ahi, Alo, n4);
    transpose_split<<<dim3(N_QKV / 32, D_MODEL / 32), dim3(32, 8)>>>(
        Wqkv, Whi, Wlo, D_MODEL, N_QKV);
    transpose_split<<<dim3(D_MODEL / 32, D_MODEL / 32), dim3(32, 8)>>>(
        Wd, Dhi, Dlo, D_MODEL, D_MODEL);
    rope_table<<<(S_LEN * 16 + 255) / 256, 256>>>();

    gemm_mma<<<dim3(N_QKV / 128, M_ROWS / 128), 256, GEMM_SMEM>>>(
        Ahi, Alo, (const uint32_t*)Whi, (const uint32_t*)Wlo,
        bqkv, qkv_p, M_ROWS, N_QKV, D_MODEL);

    qk_conv<<<(M_ROWS * H * 64) / 256, 256>>>(pos);
    v_conv<<<dim3(S_LEN / 64, H, B_SZ), 256>>>();

    flash_mma<<<dim3(S_LEN / 128, H, B_SZ), 256, FA_SMEM>>>();

    gemm_mma<<<dim3(D_MODEL / 128, M_ROWS / 128), 256, GEMM_SMEM>>>(
        Phi, Plo, (const uint32_t*)Dhi, (const uint32_t*)Dlo,
        bd, out, M_ROWS, D_MODEL, D_MODEL);
}